// round 13
// baseline (speedup 1.0000x reference)
#include <cuda_runtime.h>
#include <cstdint>

// LengthRegulator, fused gather kernel + smem-staged TMA bulk stores.
// b=16, t_x=1024, d=256, out_len=7168.
// out[b, j, :] = x[b, phoneme(j), :]; lengths[b] = sum(rep[b,:]).
//
// Output stores leave via cp.async.bulk (S2G), bypassing the L1 store path
// (L1 was the hottest unit at ~54%). Each block stages 32 contiguous output
// frames (32KB) in smem and issues ONE bulk copy.

#define B_DIM   16
#define TX      1024
#define D_DIM   256
#define OUT_LEN 7168
#define D_VEC   (D_DIM / 4)      // 64 float4 per row
#define FPT     8                // frames per 64-lane group
#define FRAMES_PER_BLK 32        // 4 groups * FPT
#define NWARP   8                // 256 threads

__global__ void __launch_bounds__(256)
fused_kernel(const float4* __restrict__ x4,
             const int*    __restrict__ rep,
             float*        __restrict__ out,
             int out_size) {
    __shared__ int s_cum[TX];
    __shared__ int s_ph[FRAMES_PER_BLK];
    __shared__ int warp_tot[NWARP];
    __shared__ __align__(16) float4 stage[FRAMES_PER_BLK * D_VEC]; // 32KB

    const int b    = blockIdx.y;
    const int base = blockIdx.x * FRAMES_PER_BLK;
    const int tid  = threadIdx.x;
    const int lane = tid & 31;
    const int wid  = tid >> 5;

    // ---- in-block scan of rep[b, :] (each thread owns 4 consecutive) ----
    const int4 r = ((const int4*)(rep + b * TX))[tid];
    const int p0 = r.x;
    const int p1 = p0 + r.y;
    const int p2 = p1 + r.z;
    const int p3 = p2 + r.w;                 // per-thread inclusive sums

    int ws = p3;                             // warp inclusive scan of p3
    #pragma unroll
    for (int off = 1; off < 32; off <<= 1) {
        int n = __shfl_up_sync(0xFFFFFFFFu, ws, off);
        if (lane >= off) ws += n;
    }
    if (lane == 31) warp_tot[wid] = ws;
    __syncthreads();

    if (wid == 0 && lane < NWARP) {          // scan the 8 warp totals
        int w = warp_tot[lane];
        #pragma unroll
        for (int off = 1; off < NWARP; off <<= 1) {
            int n = __shfl_up_sync(0xFFu, w, off);
            if (lane >= off) w += n;
        }
        warp_tot[lane] = w;                  // inclusive prefix
    }
    __syncthreads();

    const int off0 = (wid > 0 ? warp_tot[wid - 1] : 0) + (ws - p3);
    s_cum[4 * tid + 0] = off0 + p0;
    s_cum[4 * tid + 1] = off0 + p1;
    s_cum[4 * tid + 2] = off0 + p2;
    s_cum[4 * tid + 3] = off0 + p3;
    __syncthreads();

    const int total = s_cum[TX - 1];

    // lengths[b] (one block per batch writes it)
    if (blockIdx.x == 0 && tid == 0) {
        const size_t main_elems = (size_t)B_DIM * OUT_LEN * D_DIM;
        if ((size_t)out_size > main_elems)
            out[main_elems + b] = (float)total;
    }

    // ---- 32 binary searches: frame -> phoneme ----
    if (tid < FRAMES_PER_BLK) {
        const int j = base + tid;
        int ph = -1;
        if (j < total) {
            // lower_bound: first i with s_cum[i] > j; 11 iters for width 1024.
            int lo = 0, hi = TX;
            #pragma unroll
            for (int it = 0; it < 11; ++it) {
                int mid = (lo + hi) >> 1;
                if (s_cum[mid] > j) hi = mid; else lo = mid + 1;
            }
            ph = lo;
        }
        s_ph[tid] = ph;
    }
    __syncthreads();

    // ---- gather into smem staging: 4 groups of 64 lanes, FPT frames each --
    const int group = tid >> 6;              // 0..3
    const int gl    = tid & 63;
    const int f0    = group * FPT;

    int ph[FPT];
    #pragma unroll
    for (int k = 0; k < FPT; ++k) ph[k] = s_ph[f0 + k];

    float4 v[FPT];
    #pragma unroll
    for (int k = 0; k < FPT; ++k) {
        v[k] = make_float4(0.f, 0.f, 0.f, 0.f);
        if (ph[k] >= 0)
            v[k] = x4[((size_t)b * TX + ph[k]) * D_VEC + gl];
    }

    #pragma unroll
    for (int k = 0; k < FPT; ++k)
        stage[(f0 + k) * D_VEC + gl] = v[k];  // STS.128, conflict-free

    __syncthreads();
    // order the generic-proxy STS above before the async-proxy bulk read
    asm volatile("fence.proxy.async.shared::cta;" ::: "memory");

    if (tid == 0) {
        // one 32KB bulk store: smem -> global (bypasses L1 store path)
        uint64_t dst = (uint64_t)(out) +
                       ((uint64_t)b * OUT_LEN + base) * (D_DIM * 4ull);
        uint32_t src;
        asm("{ .reg .u64 t; cvta.to.shared.u64 t, %1; cvt.u32.u64 %0, t; }"
            : "=r"(src) : "l"(stage));
        asm volatile(
            "cp.async.bulk.global.shared::cta.bulk_group [%0], [%1], %2;"
            :: "l"(dst), "r"(src), "n"(FRAMES_PER_BLK * D_DIM * 4)
            : "memory");
        asm volatile("cp.async.bulk.commit_group;" ::: "memory");
        // wait only until the smem reads are done; block may then retire
        asm volatile("cp.async.bulk.wait_group.read 0;" ::: "memory");
    }
}

// ---------------------------------------------------------------------------
extern "C" void kernel_launch(void* const* d_in, const int* in_sizes, int n_in,
                              void* d_out, int out_size) {
    const float* x   = (const float*)d_in[0];   // (16,1024,256) fp32
    const int*   rep = (const int*)d_in[1];     // (16,1024) int32
    float* out = (float*)d_out;

    dim3 grid(OUT_LEN / FRAMES_PER_BLK, B_DIM); // (224, 16) = 3584 blocks
    fused_kernel<<<grid, 256>>>((const float4*)x, rep, out, out_size);
}

// round 14
// speedup vs baseline: 1.2014x; 1.2014x over previous
#include <cuda_runtime.h>
#include <cstdint>

// LengthRegulator, fused gather kernel + smem-staged TMA bulk stores with
// L2 evict_first cache hint (streaming semantics, like __stcs).
// b=16, t_x=1024, d=256, out_len=7168.
// out[b, j, :] = x[b, phoneme(j), :]; lengths[b] = sum(rep[b,:]).

#define B_DIM   16
#define TX      1024
#define D_DIM   256
#define OUT_LEN 7168
#define D_VEC   (D_DIM / 4)      // 64 float4 per row
#define FPT     8                // frames per 64-lane group
#define FRAMES_PER_BLK 32        // 4 groups * FPT
#define NWARP   8                // 256 threads

__global__ void __launch_bounds__(256)
fused_kernel(const float4* __restrict__ x4,
             const int*    __restrict__ rep,
             float*        __restrict__ out,
             int out_size) {
    __shared__ int s_cum[TX];
    __shared__ int s_ph[FRAMES_PER_BLK];
    __shared__ int warp_tot[NWARP];
    __shared__ __align__(16) float4 stage[FRAMES_PER_BLK * D_VEC]; // 32KB

    const int b    = blockIdx.y;
    const int base = blockIdx.x * FRAMES_PER_BLK;
    const int tid  = threadIdx.x;
    const int lane = tid & 31;
    const int wid  = tid >> 5;

    // ---- in-block scan of rep[b, :] (each thread owns 4 consecutive) ----
    const int4 r = ((const int4*)(rep + b * TX))[tid];
    const int p0 = r.x;
    const int p1 = p0 + r.y;
    const int p2 = p1 + r.z;
    const int p3 = p2 + r.w;                 // per-thread inclusive sums

    int ws = p3;                             // warp inclusive scan of p3
    #pragma unroll
    for (int off = 1; off < 32; off <<= 1) {
        int n = __shfl_up_sync(0xFFFFFFFFu, ws, off);
        if (lane >= off) ws += n;
    }
    if (lane == 31) warp_tot[wid] = ws;
    __syncthreads();

    if (wid == 0 && lane < NWARP) {          // scan the 8 warp totals
        int w = warp_tot[lane];
        #pragma unroll
        for (int off = 1; off < NWARP; off <<= 1) {
            int n = __shfl_up_sync(0xFFu, w, off);
            if (lane >= off) w += n;
        }
        warp_tot[lane] = w;                  // inclusive prefix
    }
    __syncthreads();

    const int off0 = (wid > 0 ? warp_tot[wid - 1] : 0) + (ws - p3);
    s_cum[4 * tid + 0] = off0 + p0;
    s_cum[4 * tid + 1] = off0 + p1;
    s_cum[4 * tid + 2] = off0 + p2;
    s_cum[4 * tid + 3] = off0 + p3;
    __syncthreads();

    const int total = s_cum[TX - 1];

    // lengths[b] (one block per batch writes it)
    if (blockIdx.x == 0 && tid == 0) {
        const size_t main_elems = (size_t)B_DIM * OUT_LEN * D_DIM;
        if ((size_t)out_size > main_elems)
            out[main_elems + b] = (float)total;
    }

    // ---- 32 binary searches: frame -> phoneme ----
    if (tid < FRAMES_PER_BLK) {
        const int j = base + tid;
        int ph = -1;
        if (j < total) {
            // lower_bound: first i with s_cum[i] > j; 11 iters for width 1024.
            int lo = 0, hi = TX;
            #pragma unroll
            for (int it = 0; it < 11; ++it) {
                int mid = (lo + hi) >> 1;
                if (s_cum[mid] > j) hi = mid; else lo = mid + 1;
            }
            ph = lo;
        }
        s_ph[tid] = ph;
    }
    __syncthreads();

    // ---- gather into smem staging: 4 groups of 64 lanes, FPT frames each --
    const int group = tid >> 6;              // 0..3
    const int gl    = tid & 63;
    const int f0    = group * FPT;

    int ph[FPT];
    #pragma unroll
    for (int k = 0; k < FPT; ++k) ph[k] = s_ph[f0 + k];

    float4 v[FPT];
    #pragma unroll
    for (int k = 0; k < FPT; ++k) {
        v[k] = make_float4(0.f, 0.f, 0.f, 0.f);
        if (ph[k] >= 0)
            v[k] = x4[((size_t)b * TX + ph[k]) * D_VEC + gl];
    }

    #pragma unroll
    for (int k = 0; k < FPT; ++k)
        stage[(f0 + k) * D_VEC + gl] = v[k];  // STS.128, conflict-free

    __syncthreads();
    // order the generic-proxy STS above before the async-proxy bulk read
    asm volatile("fence.proxy.async.shared::cta;" ::: "memory");

    if (tid == 0) {
        // one 32KB bulk store: smem -> global, L2 evict_first (streaming)
        uint64_t dst = (uint64_t)(out) +
                       ((uint64_t)b * OUT_LEN + base) * (D_DIM * 4ull);
        uint32_t src;
        asm("{ .reg .u64 t; cvta.to.shared.u64 t, %1; cvt.u32.u64 %0, t; }"
            : "=r"(src) : "l"(stage));
        asm volatile(
            "{\n\t"
            ".reg .b64 pol;\n\t"
            "createpolicy.fractional.L2::evict_first.b64 pol, 1.0;\n\t"
            "cp.async.bulk.global.shared::cta.bulk_group.L2::cache_hint "
            "[%0], [%1], %2, pol;\n\t"
            "}"
            :: "l"(dst), "r"(src), "n"(FRAMES_PER_BLK * D_DIM * 4)
            : "memory");
        asm volatile("cp.async.bulk.commit_group;" ::: "memory");
        // wait only until the smem reads are done; block may then retire
        asm volatile("cp.async.bulk.wait_group.read 0;" ::: "memory");
    }
}

// ---------------------------------------------------------------------------
extern "C" void kernel_launch(void* const* d_in, const int* in_sizes, int n_in,
                              void* d_out, int out_size) {
    const float* x   = (const float*)d_in[0];   // (16,1024,256) fp32
    const int*   rep = (const int*)d_in[1];     // (16,1024) int32
    float* out = (float*)d_out;

    dim3 grid(OUT_LEN / FRAMES_PER_BLK, B_DIM); // (224, 16) = 3584 blocks
    fused_kernel<<<grid, 256>>>((const float4*)x, rep, out, out_size);
}